// round 1
// baseline (speedup 1.0000x reference)
#include <cuda_runtime.h>

// Problem constants
#define N_TOK   (16 * 4096)   // 65536 tokens
#define DIM     256
#define NC      4096          // codebook entries

// Tiling
#define TOK_TILE   32
#define CODE_TILE  256
#define KK         8
#define THREADS    256
#define XPAD       36         // 32 tokens + 4 pad (bank-conflict-free scalar stores)
#define MAIN_GRID  (N_TOK / TOK_TILE)   // 2048

#define QELEMS  ((size_t)N_TOK * DIM)   // 16,777,216

// Scratch (allocation-free rule: __device__ globals)
__device__ float g_embedT[(size_t)NC * DIM];  // 4 MB: codebook transposed [code][dim]
__device__ float g_cnorm[NC];                 // ||e_c||^2
__device__ float g_partials[MAIN_GRID];       // per-CTA diff partial sums

// ---------------------------------------------------------------------------
// K0: precompute ||e_c||^2 and transposed codebook for coalesced gather.
// embed layout: [dim][n_embed] row-major -> embed[d*NC + c]
// ---------------------------------------------------------------------------
__global__ void prep_kernel(const float* __restrict__ embed) {
    int c = blockIdx.x * blockDim.x + threadIdx.x;   // 0..4095
    float s = 0.0f;
    #pragma unroll 8
    for (int d = 0; d < DIM; ++d) {
        float v = embed[(size_t)d * NC + c];         // coalesced across threads
        s = fmaf(v, v, s);
        g_embedT[(size_t)c * DIM + d] = v;
    }
    g_cnorm[c] = s;
}

// ---------------------------------------------------------------------------
// K1: fused  dist-GEMM + argmin + gather + quantize + diff partials
//   CTA: 32 tokens, loops over code chunks of 256.
//   Thread microtile: 4 tokens x 8 codes. Warp = one token-row -> Xs reads
//   are pure broadcast (no bank conflicts).
// ---------------------------------------------------------------------------
__global__ __launch_bounds__(THREADS, 4)
void vq_main(const float* __restrict__ x,
             const float* __restrict__ embed,
             float* __restrict__ out)
{
    __shared__ float Xs[DIM][XPAD];          // x tile, transposed: Xs[k][t]  (36 KB)
    __shared__ float Es[KK][CODE_TILE];      // codebook k-slice                (8 KB)
    __shared__ int   sidx[TOK_TILE];
    __shared__ float swred[8];

    const int tid = threadIdx.x;
    const int tokBase = blockIdx.x * TOK_TILE;

    // ---- load X tile, transposed into smem --------------------------------
    {
        int t = tid & 31;
        int g = tid >> 5;                    // warp id 0..7
        const float4* xr =
            reinterpret_cast<const float4*>(x + (size_t)(tokBase + t) * DIM);
        #pragma unroll
        for (int j = 0; j < 8; ++j) {
            int d4 = g + j * 8;              // 0..63
            float4 v = xr[d4];
            Xs[d4 * 4 + 0][t] = v.x;
            Xs[d4 * 4 + 1][t] = v.y;
            Xs[d4 * 4 + 2][t] = v.z;
            Xs[d4 * 4 + 3][t] = v.w;
        }
    }

    const int row = tid >> 5;                // warp id: tokens row*4 .. row*4+3
    const int col = tid & 31;                // codes  col*8 .. col*8+7 (within chunk)

    float best[4] = {-1e30f, -1e30f, -1e30f, -1e30f};
    int   bidx[4] = {0, 0, 0, 0};

    // ---- main loop over code chunks ---------------------------------------
    for (int c0 = 0; c0 < NC; c0 += CODE_TILE) {
        float acc[4][8];
        #pragma unroll
        for (int i = 0; i < 4; ++i)
            #pragma unroll
            for (int j = 0; j < 8; ++j)
                acc[i][j] = 0.0f;

        for (int kb = 0; kb < DIM; kb += KK) {
            __syncthreads();
            // load an 8 x 256 k-slice of embed (fully coalesced)
            {
                int kk = tid >> 5;
                int cc = (tid & 31) * 8;
                const float4* er = reinterpret_cast<const float4*>(
                    embed + (size_t)(kb + kk) * NC + c0 + cc);
                float4 a = er[0];
                float4 b = er[1];
                float4* ew = reinterpret_cast<float4*>(&Es[kk][cc]);
                ew[0] = a;
                ew[1] = b;
            }
            __syncthreads();

            #pragma unroll
            for (int kk = 0; kk < KK; ++kk) {
                const float4 xv =
                    *reinterpret_cast<const float4*>(&Xs[kb + kk][row * 4]);
                const float4 ea =
                    *reinterpret_cast<const float4*>(&Es[kk][col * 8]);
                const float4 eb =
                    *reinterpret_cast<const float4*>(&Es[kk][col * 8 + 4]);
                const float xr4[4] = {xv.x, xv.y, xv.z, xv.w};
                const float ee[8]  = {ea.x, ea.y, ea.z, ea.w,
                                      eb.x, eb.y, eb.z, eb.w};
                #pragma unroll
                for (int i = 0; i < 4; ++i)
                    #pragma unroll
                    for (int j = 0; j < 8; ++j)
                        acc[i][j] = fmaf(xr4[i], ee[j], acc[i][j]);
            }
        }

        // chunk epilogue: score = dot - 0.5*||e||^2 ; running argmax
        #pragma unroll
        for (int j = 0; j < 8; ++j) {
            int c = c0 + col * 8 + j;
            float half_cn = 0.5f * g_cnorm[c];
            #pragma unroll
            for (int i = 0; i < 4; ++i) {
                float s = acc[i][j] - half_cn;
                if (s > best[i]) { best[i] = s; bidx[i] = c; }
            }
        }
    }

    // ---- warp-level argmax reduce (32 lanes hold disjoint code subsets) ---
    #pragma unroll
    for (int i = 0; i < 4; ++i) {
        float s  = best[i];
        int   ix = bidx[i];
        #pragma unroll
        for (int off = 16; off; off >>= 1) {
            float s2 = __shfl_down_sync(0xffffffffu, s, off);
            int   i2 = __shfl_down_sync(0xffffffffu, ix, off);
            if (s2 > s || (s2 == s && i2 < ix)) { s = s2; ix = i2; }
        }
        if (col == 0) {
            int t = row * 4 + i;
            sidx[t] = ix;
            out[QELEMS + 1 + (size_t)(tokBase + t)] = (float)ix;  // embed_ind
        }
    }
    __syncthreads();

    // ---- gather quantize rows + diff partial ------------------------------
    float lsum = 0.0f;
    {
        int t  = tid >> 3;              // 0..31
        int db = (tid & 7) * 32;        // dim offset 0..224
        int idx = sidx[t];
        const float4* er = reinterpret_cast<const float4*>(
            g_embedT + (size_t)idx * DIM + db);
        float4* qw = reinterpret_cast<float4*>(
            out + (size_t)(tokBase + t) * DIM + db);
        #pragma unroll
        for (int j = 0; j < 8; ++j) {
            float4 q = er[j];
            int d = db + j * 4;
            float x0 = Xs[d + 0][t];
            float x1 = Xs[d + 1][t];
            float x2 = Xs[d + 2][t];
            float x3 = Xs[d + 3][t];
            float d0 = q.x - x0, d1 = q.y - x1, d2 = q.z - x2, d3 = q.w - x3;
            lsum = fmaf(d0, d0, lsum);
            lsum = fmaf(d1, d1, lsum);
            lsum = fmaf(d2, d2, lsum);
            lsum = fmaf(d3, d3, lsum);
            qw[j] = q;                  // quantize output (STE forward == code)
        }
    }
    #pragma unroll
    for (int off = 16; off; off >>= 1)
        lsum += __shfl_down_sync(0xffffffffu, lsum, off);
    if ((tid & 31) == 0) swred[tid >> 5] = lsum;
    __syncthreads();
    if (tid == 0) {
        float tot = 0.0f;
        #pragma unroll
        for (int w = 0; w < 8; ++w) tot += swred[w];
        g_partials[blockIdx.x] = tot;   // deterministic (no atomics)
    }
}

// ---------------------------------------------------------------------------
// K2: deterministic reduction of diff partials -> out[QELEMS]
// ---------------------------------------------------------------------------
__global__ void finalize_kernel(float* __restrict__ out) {
    __shared__ float sh[256];
    int tid = threadIdx.x;
    float s = 0.0f;
    for (int i = tid; i < MAIN_GRID; i += 256) s += g_partials[i];
    sh[tid] = s;
    __syncthreads();
    for (int off = 128; off; off >>= 1) {
        if (tid < off) sh[tid] += sh[tid + off];
        __syncthreads();
    }
    if (tid == 0)
        out[QELEMS] = sh[0] / (float)QELEMS;   // diff = mean squared error
}

// ---------------------------------------------------------------------------
extern "C" void kernel_launch(void* const* d_in, const int* in_sizes, int n_in,
                              void* d_out, int out_size) {
    const float* x     = (const float*)d_in[0];   // [16,4096,256] f32
    const float* embed = (const float*)d_in[1];   // [256,4096]    f32
    float* out = (float*)d_out;

    prep_kernel<<<NC / 256, 256>>>(embed);
    vq_main<<<MAIN_GRID, THREADS>>>(x, embed, out);
    finalize_kernel<<<1, 256>>>(out);
}

// round 3
// speedup vs baseline: 2.3019x; 2.3019x over previous
#include <cuda_runtime.h>
#include <cuda_bf16.h>
#include <cstdint>

#define N_TOK   65536
#define DIM     256
#define NC      4096
#define QELEMS  ((size_t)N_TOK * DIM)

#define M_CTA    128
#define NCHUNK   128
#define NCHUNKS  (NC / NCHUNK)          // 32
#define TOTJ     (NCHUNKS * 4)          // 128 k-block steps
#define K1_GRID  (N_TOK / M_CTA)        // 512
#define MARGIN   0.03125f

// dynamic smem layout (bytes)
#define SM_CN    0                       // 4096 f32            = 16384
#define SM_AH    16384                   // 128x256 bf16 hi     = 65536  (4 kb x 16KB)
#define SM_AL    (SM_AH + 65536)         // lo                  = 65536
#define SM_B     (SM_AL + 65536)         // 2 bufs x (16K hi + 16K lo) = 65536
#define SMEM_TOTAL (SM_B + 65536)        // 212992

// -------------------- scratch ----------------------------------------------
__device__ __nv_bfloat16 g_ebh[(size_t)NC * DIM];
__device__ __nv_bfloat16 g_ebl[(size_t)NC * DIM];
__device__ float         g_embedT[(size_t)NC * DIM];
__device__ float         g_cnh[NC];
__device__ int           g_idx[N_TOK];
__device__ int           g_flag[N_TOK];
__device__ float         g_partials[N_TOK];

// -------------------- helpers ----------------------------------------------
__device__ __forceinline__ uint32_t smem_u32(const void* p) {
    uint32_t a;
    asm("{ .reg .u64 t; cvta.to.shared.u64 t, %1; cvt.u32.u64 %0, t; }"
        : "=r"(a) : "l"(p));
    return a;
}
__device__ __forceinline__ uint32_t swz(uint32_t b) { return b ^ ((b >> 3) & 0x70); }

__device__ __forceinline__ void ldsm4(uint32_t* r, uint32_t a) {
    asm volatile("ldmatrix.sync.aligned.m8n8.x4.shared.b16 {%0,%1,%2,%3}, [%4];"
        : "=r"(r[0]), "=r"(r[1]), "=r"(r[2]), "=r"(r[3]) : "r"(a));
}
__device__ __forceinline__ void mma16816(float* c, const uint32_t* a, const uint32_t* b) {
    asm volatile("mma.sync.aligned.m16n8k16.row.col.f32.bf16.bf16.f32 "
        "{%0,%1,%2,%3}, {%4,%5,%6,%7}, {%8,%9}, {%0,%1,%2,%3};"
        : "+f"(c[0]), "+f"(c[1]), "+f"(c[2]), "+f"(c[3])
        : "r"(a[0]), "r"(a[1]), "r"(a[2]), "r"(a[3]), "r"(b[0]), "r"(b[1]));
}
__device__ __forceinline__ void cpa16(uint32_t s, const void* g) {
    asm volatile("cp.async.cg.shared.global [%0], [%1], 16;" :: "r"(s), "l"(g));
}
#define CP_COMMIT() asm volatile("cp.async.commit_group;" ::: "memory")
#define CP_WAIT1()  asm volatile("cp.async.wait_group 1;" ::: "memory")
#define CP_WAIT0()  asm volatile("cp.async.wait_group 0;" ::: "memory")

// ---------------------------------------------------------------------------
// K0a: transpose codebook + bf16 hi/lo split
// ---------------------------------------------------------------------------
__global__ void prep_transpose(const float* __restrict__ embed) {
    __shared__ float ts[64][65];
    int c0 = blockIdx.x * 64, d0 = blockIdx.y * 64;
    int a = threadIdx.x & 63, b = threadIdx.x >> 6;
    #pragma unroll
    for (int i = 0; i < 16; ++i) {
        int d = b + i * 4;
        ts[d][a] = embed[(size_t)(d0 + d) * NC + c0 + a];
    }
    __syncthreads();
    #pragma unroll
    for (int i = 0; i < 16; ++i) {
        int cI = b + i * 4;
        float v = ts[a][cI];
        size_t o = (size_t)(c0 + cI) * DIM + d0 + a;
        g_embedT[o] = v;
        __nv_bfloat16 h = __float2bfloat16(v);
        g_ebh[o] = h;
        g_ebl[o] = __float2bfloat16(v - __bfloat162float(h));
    }
}

// ---------------------------------------------------------------------------
// K0b: 0.5*||e||^2
// ---------------------------------------------------------------------------
__global__ void prep_cnorm(void) {
    int w = threadIdx.x >> 5, l = threadIdx.x & 31;
    int c = blockIdx.x * 8 + w;
    const float4* er = reinterpret_cast<const float4*>(g_embedT + (size_t)c * DIM);
    float4 p = er[l], q = er[l + 32];
    float s = p.x*p.x + p.y*p.y + p.z*p.z + p.w*p.w
            + q.x*q.x + q.y*q.y + q.z*q.z + q.w*q.w;
    #pragma unroll
    for (int off = 16; off; off >>= 1) s += __shfl_down_sync(0xffffffffu, s, off);
    if (l == 0) g_cnh[c] = 0.5f * s;
}

// ---------------------------------------------------------------------------
// K1: HMMA bf16x3 GEMM + running per-thread top-2 argmax
// ---------------------------------------------------------------------------
__global__ __launch_bounds__(256, 1)
void vq_hmma(const float* __restrict__ x) {
    extern __shared__ char smem[];
    const uint32_t sbase = smem_u32(smem);
    const int tid = threadIdx.x, lane = tid & 31, wid = tid >> 5;
    const int warp_m = wid & 3, warp_n = wid >> 2;
    const int tokBase = blockIdx.x * M_CTA;

    // cnorm -> smem
    {
        float4* cs = reinterpret_cast<float4*>(smem + SM_CN);
        const float4* cg = reinterpret_cast<const float4*>(g_cnh);
        #pragma unroll
        for (int i = 0; i < 4; ++i) cs[tid + i * 256] = cg[tid + i * 256];
    }

    // A (x tile) -> bf16 hi/lo, SW128 K-major, 4 k-blocks of 64 dims
    {
        int r = tid >> 1, half = tid & 1;
        const float4* xr = reinterpret_cast<const float4*>(x + (size_t)(tokBase + r) * DIM);
        #pragma unroll
        for (int q = 0; q < 32; ++q) {
            float4 v = xr[half * 32 + q];
            int d = half * 128 + q * 4;
            int kb = d >> 6, kd = d & 63;
            uint32_t off = kb * 16384 + swz((uint32_t)(r * 128 + kd * 2));
            __nv_bfloat16 h0 = __float2bfloat16(v.x), h1 = __float2bfloat16(v.y);
            __nv_bfloat16 h2 = __float2bfloat16(v.z), h3 = __float2bfloat16(v.w);
            uint32_t ph0 = ((uint32_t)__bfloat16_as_ushort(h1) << 16) | __bfloat16_as_ushort(h0);
            uint32_t ph1 = ((uint32_t)__bfloat16_as_ushort(h3) << 16) | __bfloat16_as_ushort(h2);
            *reinterpret_cast<uint32_t*>(smem + SM_AH + off)     = ph0;
            *reinterpret_cast<uint32_t*>(smem + SM_AH + off + 4) = ph1;
            __nv_bfloat16 l0 = __float2bfloat16(v.x - __bfloat162float(h0));
            __nv_bfloat16 l1 = __float2bfloat16(v.y - __bfloat162float(h1));
            __nv_bfloat16 l2 = __float2bfloat16(v.z - __bfloat162float(h2));
            __nv_bfloat16 l3 = __float2bfloat16(v.w - __bfloat162float(h3));
            uint32_t pl0 = ((uint32_t)__bfloat16_as_ushort(l1) << 16) | __bfloat16_as_ushort(l0);
            uint32_t pl1 = ((uint32_t)__bfloat16_as_ushort(l3) << 16) | __bfloat16_as_ushort(l2);
            *reinterpret_cast<uint32_t*>(smem + SM_AL + off)     = pl0;
            *reinterpret_cast<uint32_t*>(smem + SM_AL + off + 4) = pl1;
        }
    }
    __syncthreads();

    const float* cnh = reinterpret_cast<const float*>(smem + SM_CN);

    float acc[2][8][4];
    float best[4], sec[4];
    int   bi[4];
    #pragma unroll
    for (int i = 0; i < 4; ++i) { best[i] = -1e30f; sec[i] = -1e30f; bi[i] = 0; }

    const int seg = tid & 7, rb = tid >> 3;

    // B k-block loader (cp.async, 128 codes x 64 dims, hi+lo)
    auto loadB = [&](int j) {
        int c0 = (j >> 2) * NCHUNK, kb = j & 3;
        uint32_t bb = sbase + SM_B + (j & 1) * 32768;
        #pragma unroll
        for (int i = 0; i < 4; ++i) {
            int row = rb + 32 * i;
            size_t go = ((size_t)(c0 + row) << 8) + kb * 64 + seg * 8;
            uint32_t so = swz((uint32_t)(row * 128 + seg * 16));
            cpa16(bb + so,         g_ebh + go);
            cpa16(bb + 16384 + so, g_ebl + go);
        }
    };

    loadB(0);
    CP_COMMIT();

    const int r16 = lane & 15, cg8 = (lane >> 4) << 3;

    for (int j = 0; j < TOTJ; ++j) {
        if (j + 1 < TOTJ) { loadB(j + 1); CP_COMMIT(); CP_WAIT1(); }
        else              { CP_WAIT0(); }
        __syncthreads();

        const int kb = j & 3;
        const uint32_t aH = sbase + SM_AH + kb * 16384;
        const uint32_t aL = sbase + SM_AL + kb * 16384;
        const uint32_t bH = sbase + SM_B + (j & 1) * 32768;
        const uint32_t bL = bH + 16384;

        if (kb == 0) {
            #pragma unroll
            for (int mt = 0; mt < 2; ++mt)
                #pragma unroll
                for (int nt = 0; nt < 8; ++nt)
                    #pragma unroll
                    for (int e = 0; e < 4; ++e) acc[mt][nt][e] = 0.0f;
        }

        #pragma unroll
        for (int ks = 0; ks < 4; ++ks) {
            const int kcol = ks * 16 + cg8;
            uint32_t ah[2][4], al[2][4], bh[8][2], bl[8][2];
            #pragma unroll
            for (int mt = 0; mt < 2; ++mt) {
                uint32_t off = swz((uint32_t)((warp_m * 32 + mt * 16 + r16) * 128 + kcol * 2));
                ldsm4(ah[mt], aH + off);
                ldsm4(al[mt], aL + off);
            }
            #pragma unroll
            for (int p = 0; p < 4; ++p) {
                uint32_t off = swz((uint32_t)((warp_n * 64 + p * 16 + r16) * 128 + kcol * 2));
                uint32_t t[4];
                ldsm4(t, bH + off);
                bh[2*p][0] = t[0]; bh[2*p][1] = t[2];
                bh[2*p+1][0] = t[1]; bh[2*p+1][1] = t[3];
                ldsm4(t, bL + off);
                bl[2*p][0] = t[0]; bl[2*p][1] = t[2];
                bl[2*p+1][0] = t[1]; bl[2*p+1][1] = t[3];
            }
            // 3 passes: Ah*Bh, Ah*Bl, Al*Bh — long independent chains
            #pragma unroll
            for (int mt = 0; mt < 2; ++mt)
                #pragma unroll
                for (int nt = 0; nt < 8; ++nt)
                    mma16816(acc[mt][nt], ah[mt], bh[nt]);
            #pragma unroll
            for (int mt = 0; mt < 2; ++mt)
                #pragma unroll
                for (int nt = 0; nt < 8; ++nt)
                    mma16816(acc[mt][nt], ah[mt], bl[nt]);
            #pragma unroll
            for (int mt = 0; mt < 2; ++mt)
                #pragma unroll
                for (int nt = 0; nt < 8; ++nt)
                    mma16816(acc[mt][nt], al[mt], bh[nt]);
        }

        if (kb == 3) {
            // chunk epilogue: scores + per-thread running top-2
            const int c0 = (j >> 2) * NCHUNK + warp_n * 64 + (lane & 3) * 2;
            #pragma unroll
            for (int nt = 0; nt < 8; ++nt) {
                const int col0 = c0 + nt * 8;
                const float cn0 = cnh[col0], cn1 = cnh[col0 + 1];
                #pragma unroll
                for (int mt = 0; mt < 2; ++mt) {
                    const int s0 = mt * 2, s1 = mt * 2 + 1;
                    float v;
                    v = acc[mt][nt][0] - cn0;
                    if (v > best[s0]) { sec[s0] = best[s0]; best[s0] = v; bi[s0] = col0; }
                    else if (v > sec[s0]) sec[s0] = v;
                    v = acc[mt][nt][1] - cn1;
                    if (v > best[s0]) { sec[s0] = best[s0]; best[s0] = v; bi[s0] = col0 + 1; }
                    else if (v > sec[s0]) sec[s0] = v;
                    v = acc[mt][nt][2] - cn0;
                    if (v > best[s1]) { sec[s1] = best[s1]; best[s1] = v; bi[s1] = col0; }
                    else if (v > sec[s1]) sec[s1] = v;
                    v = acc[mt][nt][3] - cn1;
                    if (v > best[s1]) { sec[s1] = best[s1]; best[s1] = v; bi[s1] = col0 + 1; }
                    else if (v > sec[s1]) sec[s1] = v;
                }
            }
        }
        __syncthreads();
    }

    // ---- final top-2 reduction ----
    // intra-quad (4 lanes share a row)
    #pragma unroll
    for (int s = 0; s < 4; ++s) {
        float b = best[s], se = sec[s];
        int   i = bi[s];
        #pragma unroll
        for (int off = 1; off <= 2; off <<= 1) {
            float ob = __shfl_xor_sync(0xffffffffu, b, off);
            float os = __shfl_xor_sync(0xffffffffu, se, off);
            int   oi = __shfl_xor_sync(0xffffffffu, i, off);
            if (ob > b || (ob == b && oi < i)) {
                se = fmaxf(b, os); b = ob; i = oi;
            } else {
                se = fmaxf(se, ob);
            }
        }
        best[s] = b; sec[s] = se; bi[s] = i;
    }

    // cross warp_n merge via smem (reuse B region; all cp.async drained)
    float* mb = reinterpret_cast<float*>(smem + SM_B);
    float* ms = mb + 128;
    int*   mi = reinterpret_cast<int*>(ms + 128);
    if (warp_n == 0 && (lane & 3) == 0) {
        #pragma unroll
        for (int s = 0; s < 4; ++s) {
            int row = warp_m * 32 + (s >> 1) * 16 + (s & 1) * 8 + (lane >> 2);
            mb[row] = best[s]; ms[row] = sec[s]; mi[row] = bi[s];
        }
    }
    __syncthreads();
    if (warp_n == 1 && (lane & 3) == 0) {
        #pragma unroll
        for (int s = 0; s < 4; ++s) {
            int row = warp_m * 32 + (s >> 1) * 16 + (s & 1) * 8 + (lane >> 2);
            float b = best[s], se = sec[s];
            int   i = bi[s];
            float ob = mb[row], os = ms[row];
            int   oi = mi[row];
            if (ob > b || (ob == b && oi < i)) {
                se = fmaxf(b, os); b = ob; i = oi;
            } else {
                se = fmaxf(se, ob);
            }
            int t = tokBase + row;
            g_idx[t]  = i;
            g_flag[t] = (b - se < MARGIN) ? 1 : 0;
        }
    }
}

// ---------------------------------------------------------------------------
// K2: exact fp32 rescore of flagged tokens (one warp per token)
// ---------------------------------------------------------------------------
__global__ __launch_bounds__(256)
void fixup_kernel(const float* __restrict__ x) {
    __shared__ float xs[8][256];
    int w = threadIdx.x >> 5, l = threadIdx.x & 31;
    int t = blockIdx.x * 8 + w;
    if (!g_flag[t]) return;
    float4* xv = reinterpret_cast<float4*>(xs[w]);
    const float4* xr = reinterpret_cast<const float4*>(x + (size_t)t * DIM);
    xv[l] = xr[l];
    xv[l + 32] = xr[l + 32];
    __syncwarp();
    float best = -1e30f; int bi = 0;
    for (int i = 0; i < 128; ++i) {
        int cc = l + 32 * i;
        const float4* er = reinterpret_cast<const float4*>(g_embedT + (size_t)cc * DIM);
        float s = 0.0f;
        #pragma unroll 8
        for (int d = 0; d < 64; ++d) {
            float4 e = er[d], xq = xv[d];
            s = fmaf(e.x, xq.x, s); s = fmaf(e.y, xq.y, s);
            s = fmaf(e.z, xq.z, s); s = fmaf(e.w, xq.w, s);
        }
        s -= g_cnh[cc];
        if (s > best) { best = s; bi = cc; }
    }
    #pragma unroll
    for (int off = 16; off; off >>= 1) {
        float s2 = __shfl_down_sync(0xffffffffu, best, off);
        int   i2 = __shfl_down_sync(0xffffffffu, bi, off);
        if (s2 > best || (s2 == best && i2 < bi)) { best = s2; bi = i2; }
    }
    if (l == 0) g_idx[t] = bi;
}

// ---------------------------------------------------------------------------
// K3: gather quantize + diff partials + indices (one warp per token)
// ---------------------------------------------------------------------------
__global__ __launch_bounds__(256)
void quantize_kernel(const float* __restrict__ x, float* __restrict__ out) {
    int gt = blockIdx.x * 8 + (threadIdx.x >> 5);
    int l = threadIdx.x & 31;
    int idx = g_idx[gt];
    const float4* er = reinterpret_cast<const float4*>(g_embedT + (size_t)idx * DIM);
    const float4* xr = reinterpret_cast<const float4*>(x + (size_t)gt * DIM);
    float4* qw = reinterpret_cast<float4*>(out + (size_t)gt * DIM);
    float s = 0.0f;
    #pragma unroll
    for (int i = 0; i < 2; ++i) {
        int k = l + 32 * i;
        float4 q = er[k], xv = xr[k];
        float d0 = q.x - xv.x, d1 = q.y - xv.y, d2 = q.z - xv.z, d3 = q.w - xv.w;
        s = fmaf(d0, d0, s); s = fmaf(d1, d1, s);
        s = fmaf(d2, d2, s); s = fmaf(d3, d3, s);
        qw[k] = q;
    }
    #pragma unroll
    for (int off = 16; off; off >>= 1) s += __shfl_down_sync(0xffffffffu, s, off);
    if (l == 0) {
        g_partials[gt] = s;
        out[QELEMS + 1 + (size_t)gt] = (float)idx;
    }
}

// ---------------------------------------------------------------------------
// K4: deterministic diff reduction
// ---------------------------------------------------------------------------
__global__ void finalize_kernel(float* __restrict__ out) {
    __shared__ float sh[256];
    int tid = threadIdx.x;
    const float4* p4 = reinterpret_cast<const float4*>(g_partials);
    float s = 0.0f;
    for (int j = 0; j < 64; ++j) {
        float4 v = p4[tid + 256 * j];
        s += v.x + v.y + v.z + v.w;
    }
    sh[tid] = s;
    __syncthreads();
    for (int off = 128; off; off >>= 1) {
        if (tid < off) sh[tid] += sh[tid + off];
        __syncthreads();
    }
    if (tid == 0) out[QELEMS] = sh[0] / (float)QELEMS;
}

// ---------------------------------------------------------------------------
extern "C" void kernel_launch(void* const* d_in, const int* in_sizes, int n_in,
                              void* d_out, int out_size) {
    const float* x     = (const float*)d_in[0];
    const float* embed = (const float*)d_in[1];
    float* out = (float*)d_out;

    cudaFuncSetAttribute(vq_hmma, cudaFuncAttributeMaxDynamicSharedMemorySize,
                         SMEM_TOTAL);

    prep_transpose<<<dim3(NC / 64, DIM / 64), 256>>>(embed);
    prep_cnorm<<<NC / 8, 256>>>();
    vq_hmma<<<K1_GRID, 256, SMEM_TOTAL>>>(x);
    fixup_kernel<<<N_TOK / 8, 256>>>(x);
    quantize_kernel<<<N_TOK / 8, 256>>>(x, out);
    finalize_kernel<<<1, 256>>>(out);
}

// round 4
// speedup vs baseline: 5.1631x; 2.2430x over previous
#include <cuda_runtime.h>
#include <cuda_fp16.h>
#include <cstdint>

#define N_TOK   65536
#define DIM     256
#define NC      4096
#define QELEMS  ((size_t)N_TOK * DIM)

#define M_CTA    128
#define NCHUNK   128
#define NCHUNKS  (NC / NCHUNK)          // 32
#define TOTJ     (NCHUNKS * 4)          // 128 k-block steps
#define K1_GRID  (N_TOK / M_CTA)        // 512
#define MARGIN   0.0625f

// K1 dynamic smem layout (bytes)
#define SM_CN    0                       // 4096 f32 = 16384
#define SM_A     16384                   // 128x256 fp16 = 65536 (4 kb x 16KB)
#define SM_B     (SM_A + 65536)          // 4 stages x 16KB = 65536
#define SMEM_TOTAL (SM_B + 65536)        // 147456

// -------------------- scratch ----------------------------------------------
__device__ __half g_ebh[(size_t)NC * DIM];          // fp16 codebook [code][dim]
__device__ float  g_embedT[(size_t)NC * DIM];       // fp32 codebook [code][dim]
__device__ float  g_cnh[NC];                        // 0.5*||e||^2
__device__ int    g_idx[N_TOK];
__device__ float  g_partials[N_TOK];
__device__ int    g_count;
__device__ int    g_list[N_TOK];

// -------------------- helpers ----------------------------------------------
__device__ __forceinline__ uint32_t smem_u32(const void* p) {
    uint32_t a;
    asm("{ .reg .u64 t; cvta.to.shared.u64 t, %1; cvt.u32.u64 %0, t; }"
        : "=r"(a) : "l"(p));
    return a;
}
__device__ __forceinline__ uint32_t swz(uint32_t b) { return b ^ ((b >> 3) & 0x70); }

__device__ __forceinline__ void ldsm4(uint32_t* r, uint32_t a) {
    asm volatile("ldmatrix.sync.aligned.m8n8.x4.shared.b16 {%0,%1,%2,%3}, [%4];"
        : "=r"(r[0]), "=r"(r[1]), "=r"(r[2]), "=r"(r[3]) : "r"(a));
}
__device__ __forceinline__ void mma16816(float* c, const uint32_t* a, const uint32_t* b) {
    asm volatile("mma.sync.aligned.m16n8k16.row.col.f32.f16.f16.f32 "
        "{%0,%1,%2,%3}, {%4,%5,%6,%7}, {%8,%9}, {%0,%1,%2,%3};"
        : "+f"(c[0]), "+f"(c[1]), "+f"(c[2]), "+f"(c[3])
        : "r"(a[0]), "r"(a[1]), "r"(a[2]), "r"(a[3]), "r"(b[0]), "r"(b[1]));
}
__device__ __forceinline__ void cpa16(uint32_t s, const void* g) {
    asm volatile("cp.async.cg.shared.global [%0], [%1], 16;" :: "r"(s), "l"(g));
}
#define CP_COMMIT() asm volatile("cp.async.commit_group;" ::: "memory")
#define CP_WAIT2()  asm volatile("cp.async.wait_group 2;" ::: "memory")
#define CP_WAIT1()  asm volatile("cp.async.wait_group 1;" ::: "memory")
#define CP_WAIT0()  asm volatile("cp.async.wait_group 0;" ::: "memory")

// ---------------------------------------------------------------------------
// K0a: transpose codebook + fp16 cast; zero compaction counter
// ---------------------------------------------------------------------------
__global__ void prep_transpose(const float* __restrict__ embed) {
    __shared__ float ts[64][65];
    if (blockIdx.x == 0 && blockIdx.y == 0 && threadIdx.x == 0) g_count = 0;
    int c0 = blockIdx.x * 64, d0 = blockIdx.y * 64;
    int a = threadIdx.x & 63, b = threadIdx.x >> 6;
    #pragma unroll
    for (int i = 0; i < 16; ++i) {
        int d = b + i * 4;
        ts[d][a] = embed[(size_t)(d0 + d) * NC + c0 + a];
    }
    __syncthreads();
    #pragma unroll
    for (int i = 0; i < 16; ++i) {
        int cI = b + i * 4;
        float v = ts[a][cI];
        size_t o = (size_t)(c0 + cI) * DIM + d0 + a;
        g_embedT[o] = v;
        g_ebh[o] = __float2half_rn(v);
    }
}

// ---------------------------------------------------------------------------
// K0b: 0.5*||e||^2
// ---------------------------------------------------------------------------
__global__ void prep_cnorm(void) {
    int w = threadIdx.x >> 5, l = threadIdx.x & 31;
    int c = blockIdx.x * 8 + w;
    const float4* er = reinterpret_cast<const float4*>(g_embedT + (size_t)c * DIM);
    float4 p = er[l], q = er[l + 32];
    float s = p.x*p.x + p.y*p.y + p.z*p.z + p.w*p.w
            + q.x*q.x + q.y*q.y + q.z*q.z + q.w*q.w;
    #pragma unroll
    for (int off = 16; off; off >>= 1) s += __shfl_down_sync(0xffffffffu, s, off);
    if (l == 0) g_cnh[c] = 0.5f * s;
}

// ---------------------------------------------------------------------------
// K1: fp16 single-pass HMMA GEMM + running top-2 argmax + flag compaction
// ---------------------------------------------------------------------------
__global__ __launch_bounds__(256, 1)
void vq_hmma(const float* __restrict__ x) {
    extern __shared__ char smem[];
    const uint32_t sbase = smem_u32(smem);
    const int tid = threadIdx.x, lane = tid & 31, wid = tid >> 5;
    const int warp_m = wid & 3, warp_n = wid >> 2;
    const int tokBase = blockIdx.x * M_CTA;

    // cnorm -> smem
    {
        float4* cs = reinterpret_cast<float4*>(smem + SM_CN);
        const float4* cg = reinterpret_cast<const float4*>(g_cnh);
        #pragma unroll
        for (int i = 0; i < 4; ++i) cs[tid + i * 256] = cg[tid + i * 256];
    }

    // A (x tile) -> fp16, SW128 K-major, 4 k-blocks of 64 dims
    {
        int r = tid >> 1, half = tid & 1;
        const float4* xr = reinterpret_cast<const float4*>(x + (size_t)(tokBase + r) * DIM);
        #pragma unroll
        for (int q = 0; q < 32; ++q) {
            float4 v = xr[half * 32 + q];
            int d = half * 128 + q * 4;
            int kb = d >> 6, kd = d & 63;
            uint32_t off = kb * 16384 + swz((uint32_t)(r * 128 + kd * 2));
            __half h0 = __float2half_rn(v.x), h1 = __float2half_rn(v.y);
            __half h2 = __float2half_rn(v.z), h3 = __float2half_rn(v.w);
            uint32_t p0 = ((uint32_t)__half_as_ushort(h1) << 16) | __half_as_ushort(h0);
            uint32_t p1 = ((uint32_t)__half_as_ushort(h3) << 16) | __half_as_ushort(h2);
            *reinterpret_cast<uint32_t*>(smem + SM_A + off)     = p0;
            *reinterpret_cast<uint32_t*>(smem + SM_A + off + 4) = p1;
        }
    }
    __syncthreads();

    const float* cnh = reinterpret_cast<const float*>(smem + SM_CN);

    float acc[2][8][4];
    float best[4], sec[4];
    int   bi[4];
    #pragma unroll
    for (int i = 0; i < 4; ++i) { best[i] = -1e30f; sec[i] = -1e30f; bi[i] = 0; }

    const int seg = tid & 7, rb = tid >> 3;

    // B k-block loader: 128 codes x 64 dims fp16 = 16KB into stage j&3
    auto loadB = [&](int j) {
        int c0 = (j >> 2) * NCHUNK, kb = j & 3;
        uint32_t bb = sbase + SM_B + (j & 3) * 16384;
        #pragma unroll
        for (int i = 0; i < 4; ++i) {
            int row = rb + 32 * i;
            size_t go = ((size_t)(c0 + row) << 8) + kb * 64 + seg * 8;
            uint32_t so = swz((uint32_t)(row * 128 + seg * 16));
            cpa16(bb + so, g_ebh + go);
        }
    };

    loadB(0); CP_COMMIT();
    loadB(1); CP_COMMIT();
    loadB(2); CP_COMMIT();

    const int r16 = lane & 15, cg8 = (lane >> 4) << 3;

    for (int j = 0; j < TOTJ; ++j) {
        int rem = TOTJ - 1 - j;
        if (rem >= 2)      CP_WAIT2();
        else if (rem == 1) CP_WAIT1();
        else               CP_WAIT0();
        __syncthreads();                 // stage j visible; compute j-1 done everywhere
        if (j + 3 < TOTJ) { loadB(j + 3); CP_COMMIT(); }

        const int kb = j & 3;
        const uint32_t aB = sbase + SM_A + kb * 16384;
        const uint32_t bB = sbase + SM_B + (j & 3) * 16384;

        if (kb == 0) {
            #pragma unroll
            for (int mt = 0; mt < 2; ++mt)
                #pragma unroll
                for (int nt = 0; nt < 8; ++nt)
                    #pragma unroll
                    for (int e = 0; e < 4; ++e) acc[mt][nt][e] = 0.0f;
        }

        #pragma unroll
        for (int ks = 0; ks < 4; ++ks) {
            const int kcol = ks * 16 + cg8;
            uint32_t ah[2][4], bh[8][2];
            #pragma unroll
            for (int mt = 0; mt < 2; ++mt) {
                uint32_t off = swz((uint32_t)((warp_m * 32 + mt * 16 + r16) * 128 + kcol * 2));
                ldsm4(ah[mt], aB + off);
            }
            #pragma unroll
            for (int p = 0; p < 4; ++p) {
                uint32_t off = swz((uint32_t)((warp_n * 64 + p * 16 + r16) * 128 + kcol * 2));
                uint32_t t[4];
                ldsm4(t, bB + off);
                bh[2*p][0]   = t[0]; bh[2*p][1]   = t[2];
                bh[2*p+1][0] = t[1]; bh[2*p+1][1] = t[3];
            }
            #pragma unroll
            for (int mt = 0; mt < 2; ++mt)
                #pragma unroll
                for (int nt = 0; nt < 8; ++nt)
                    mma16816(acc[mt][nt], ah[mt], bh[nt]);
        }

        if (kb == 3) {
            const int c0 = (j >> 2) * NCHUNK + warp_n * 64 + (lane & 3) * 2;
            #pragma unroll
            for (int nt = 0; nt < 8; ++nt) {
                const int col0 = c0 + nt * 8;
                const float cn0 = cnh[col0], cn1 = cnh[col0 + 1];
                #pragma unroll
                for (int mt = 0; mt < 2; ++mt) {
                    const int s0 = mt * 2, s1 = mt * 2 + 1;
                    float v;
                    v = acc[mt][nt][0] - cn0;
                    if (v > best[s0]) { sec[s0] = best[s0]; best[s0] = v; bi[s0] = col0; }
                    else if (v > sec[s0]) sec[s0] = v;
                    v = acc[mt][nt][1] - cn1;
                    if (v > best[s0]) { sec[s0] = best[s0]; best[s0] = v; bi[s0] = col0 + 1; }
                    else if (v > sec[s0]) sec[s0] = v;
                    v = acc[mt][nt][2] - cn0;
                    if (v > best[s1]) { sec[s1] = best[s1]; best[s1] = v; bi[s1] = col0; }
                    else if (v > sec[s1]) sec[s1] = v;
                    v = acc[mt][nt][3] - cn1;
                    if (v > best[s1]) { sec[s1] = best[s1]; best[s1] = v; bi[s1] = col0 + 1; }
                    else if (v > sec[s1]) sec[s1] = v;
                }
            }
        }
    }
    __syncthreads();   // all cp.async drained (wait0 at last iter); SM_B reusable

    // intra-quad top-2 merge (4 lanes share a row)
    #pragma unroll
    for (int s = 0; s < 4; ++s) {
        float b = best[s], se = sec[s];
        int   i = bi[s];
        #pragma unroll
        for (int off = 1; off <= 2; off <<= 1) {
            float ob = __shfl_xor_sync(0xffffffffu, b, off);
            float os = __shfl_xor_sync(0xffffffffu, se, off);
            int   oi = __shfl_xor_sync(0xffffffffu, i, off);
            if (ob > b || (ob == b && oi < i)) { se = fmaxf(b, os); b = ob; i = oi; }
            else                               { se = fmaxf(se, ob); }
        }
        best[s] = b; sec[s] = se; bi[s] = i;
    }

    // cross warp_n merge via smem
    float* mb = reinterpret_cast<float*>(smem + SM_B);
    float* ms = mb + 128;
    int*   mi = reinterpret_cast<int*>(ms + 128);
    if (warp_n == 0 && (lane & 3) == 0) {
        #pragma unroll
        for (int s = 0; s < 4; ++s) {
            int row = warp_m * 32 + (s >> 1) * 16 + (s & 1) * 8 + (lane >> 2);
            mb[row] = best[s]; ms[row] = sec[s]; mi[row] = bi[s];
        }
    }
    __syncthreads();
    if (warp_n == 1 && (lane & 3) == 0) {
        #pragma unroll
        for (int s = 0; s < 4; ++s) {
            int row = warp_m * 32 + (s >> 1) * 16 + (s & 1) * 8 + (lane >> 2);
            float b = best[s], se = sec[s];
            int   i = bi[s];
            float ob = mb[row], os = ms[row];
            int   oi = mi[row];
            if (ob > b || (ob == b && oi < i)) { se = fmaxf(b, os); b = ob; i = oi; }
            else                               { se = fmaxf(se, ob); }
            int t = tokBase + row;
            g_idx[t] = i;
            if (b - se < MARGIN) {
                int p = atomicAdd(&g_count, 1);
                g_list[p] = t;
            }
        }
    }
}

// ---------------------------------------------------------------------------
// K2: exact fp32 rescore of flagged tokens.
//     CTA = 8 tokens x 4096 codes; codebook streamed once through smem.
// ---------------------------------------------------------------------------
__global__ __launch_bounds__(256)
void fixup_micro(const float* __restrict__ x) {
    int cnt = g_count;
    int nb = (cnt + 7) >> 3;
    if ((int)blockIdx.x >= nb) return;

    __shared__ float Xs[256][8];     // [dim][tok] (reads broadcast)
    __shared__ float Es[8][1024];    // one 8-dim k-slice of 1024 codes
    __shared__ int   toks[8];
    __shared__ float wb[8][8];       // [warp][tok] merge
    __shared__ int   wi[8][8];

    const int tid = threadIdx.x, lane = tid & 31, wid = tid >> 5;

    if (tid < 8) {
        int li = blockIdx.x * 8 + tid;
        toks[tid] = g_list[li < cnt ? li : 0];
    }
    __syncthreads();
    {
        int tk = tid & 7, d0 = (tid >> 3) * 8;
        const float* xr = x + (size_t)toks[tk] * DIM + d0;
        #pragma unroll
        for (int i = 0; i < 8; ++i) Xs[d0 + i][tk] = xr[i];
    }

    float best[8]; int bi[8];
    #pragma unroll
    for (int t = 0; t < 8; ++t) { best[t] = -1e30f; bi[t] = 0; }

    for (int cc = 0; cc < 4; ++cc) {            // 1024-code chunks
        float acc[8][4];
        #pragma unroll
        for (int t = 0; t < 8; ++t)
            #pragma unroll
            for (int jj = 0; jj < 4; ++jj) acc[t][jj] = 0.0f;

        for (int k0 = 0; k0 < DIM; k0 += 8) {
            __syncthreads();
            // load slice: Es[k][c] = embedT[cc*1024+c][k0+k]; conflict-free stores
            #pragma unroll
            for (int jj = 0; jj < 4; ++jj) {
                int c = tid + 256 * jj;
                const float4* er = reinterpret_cast<const float4*>(
                    g_embedT + (size_t)(cc * 1024 + c) * DIM + k0);
                float4 a = er[0], b = er[1];
                Es[0][c] = a.x; Es[1][c] = a.y; Es[2][c] = a.z; Es[3][c] = a.w;
                Es[4][c] = b.x; Es[5][c] = b.y; Es[6][c] = b.z; Es[7][c] = b.w;
            }
            __syncthreads();
            #pragma unroll
            for (int kk = 0; kk < 8; ++kk) {
                float4 e4 = *reinterpret_cast<const float4*>(&Es[kk][tid * 4]);
                float xv[8];
                #pragma unroll
                for (int t = 0; t < 8; ++t) xv[t] = Xs[k0 + kk][t];
                #pragma unroll
                for (int t = 0; t < 8; ++t) {
                    acc[t][0] = fmaf(xv[t], e4.x, acc[t][0]);
                    acc[t][1] = fmaf(xv[t], e4.y, acc[t][1]);
                    acc[t][2] = fmaf(xv[t], e4.z, acc[t][2]);
                    acc[t][3] = fmaf(xv[t], e4.w, acc[t][3]);
                }
            }
        }
        #pragma unroll
        for (int jj = 0; jj < 4; ++jj) {
            int c = cc * 1024 + tid * 4 + jj;
            float cn = g_cnh[c];
            #pragma unroll
            for (int t = 0; t < 8; ++t) {
                float s = acc[t][jj] - cn;
                if (s > best[t] || (s == best[t] && c < bi[t])) { best[t] = s; bi[t] = c; }
            }
        }
    }

    // reduce across threads per token
    #pragma unroll
    for (int t = 0; t < 8; ++t) {
        float b = best[t]; int i = bi[t];
        #pragma unroll
        for (int off = 16; off; off >>= 1) {
            float ob = __shfl_down_sync(0xffffffffu, b, off);
            int   oi = __shfl_down_sync(0xffffffffu, i, off);
            if (ob > b || (ob == b && oi < i)) { b = ob; i = oi; }
        }
        if (lane == 0) { wb[wid][t] = b; wi[wid][t] = i; }
    }
    __syncthreads();
    if (wid == 0 && lane < 8) {
        int t = lane;
        float b = wb[0][t]; int i = wi[0][t];
        #pragma unroll
        for (int w = 1; w < 8; ++w) {
            float ob = wb[w][t]; int oi = wi[w][t];
            if (ob > b || (ob == b && oi < i)) { b = ob; i = oi; }
        }
        g_idx[toks[t]] = i;
    }
}

// ---------------------------------------------------------------------------
// K3: gather quantize + diff partials + indices
// ---------------------------------------------------------------------------
__global__ __launch_bounds__(256)
void quantize_kernel(const float* __restrict__ x, float* __restrict__ out) {
    int gt = blockIdx.x * 8 + (threadIdx.x >> 5);
    int l = threadIdx.x & 31;
    int idx = g_idx[gt];
    const float4* er = reinterpret_cast<const float4*>(g_embedT + (size_t)idx * DIM);
    const float4* xr = reinterpret_cast<const float4*>(x + (size_t)gt * DIM);
    float4* qw = reinterpret_cast<float4*>(out + (size_t)gt * DIM);
    float s = 0.0f;
    #pragma unroll
    for (int i = 0; i < 2; ++i) {
        int k = l + 32 * i;
        float4 q = er[k], xv = xr[k];
        float d0 = q.x - xv.x, d1 = q.y - xv.y, d2 = q.z - xv.z, d3 = q.w - xv.w;
        s = fmaf(d0, d0, s); s = fmaf(d1, d1, s);
        s = fmaf(d2, d2, s); s = fmaf(d3, d3, s);
        qw[k] = q;
    }
    #pragma unroll
    for (int off = 16; off; off >>= 1) s += __shfl_down_sync(0xffffffffu, s, off);
    if (l == 0) {
        g_partials[gt] = s;
        out[QELEMS + 1 + (size_t)gt] = (float)idx;
    }
}

// ---------------------------------------------------------------------------
// K4: deterministic diff reduction
// ---------------------------------------------------------------------------
__global__ void finalize_kernel(float* __restrict__ out) {
    __shared__ float sh[256];
    int tid = threadIdx.x;
    const float4* p4 = reinterpret_cast<const float4*>(g_partials);
    float s = 0.0f;
    for (int j = 0; j < 64; ++j) {
        float4 v = p4[tid + 256 * j];
        s += v.x + v.y + v.z + v.w;
    }
    sh[tid] = s;
    __syncthreads();
    for (int off = 128; off; off >>= 1) {
        if (tid < off) sh[tid] += sh[tid + off];
        __syncthreads();
    }
    if (tid == 0) out[QELEMS] = sh[0] / (float)QELEMS;
}

// ---------------------------------------------------------------------------
extern "C" void kernel_launch(void* const* d_in, const int* in_sizes, int n_in,
                              void* d_out, int out_size) {
    const float* x     = (const float*)d_in[0];
    const float* embed = (const float*)d_in[1];
    float* out = (float*)d_out;

    cudaFuncSetAttribute(vq_hmma, cudaFuncAttributeMaxDynamicSharedMemorySize,
                         SMEM_TOTAL);

    prep_transpose<<<dim3(NC / 64, DIM / 64), 256>>>(embed);
    prep_cnorm<<<NC / 8, 256>>>();
    vq_hmma<<<K1_GRID, 256, SMEM_TOTAL>>>(x);
    fixup_micro<<<N_TOK / 8, 256>>>(x);
    quantize_kernel<<<N_TOK / 8, 256>>>(x, out);
    finalize_kernel<<<1, 256>>>(out);
}

// round 5
// speedup vs baseline: 6.7020x; 1.2980x over previous
#include <cuda_runtime.h>
#include <cuda_fp16.h>
#include <cstdint>

#define N_TOK   65536
#define DIM     256
#define NC      4096
#define QELEMS  ((size_t)N_TOK * DIM)

#define M_CTA    128
#define NCHUNK   128
#define NCHUNKS  (NC / NCHUNK)          // 32
#define TOTJ     (NCHUNKS * 4)          // 128 k-block steps
#define K1_GRID  (N_TOK / M_CTA)        // 512
#define MARGIN   0.05f

// K1 dynamic smem layout (bytes)
#define SM_CN    0                       // 4096 f32 = 16384
#define SM_A     16384                   // 128x256 fp16 = 65536 (4 kb x 16KB)
#define SM_B     (SM_A + 65536)          // 4 stages x 16KB = 65536
#define SMEM_TOTAL (SM_B + 65536)        // 147456

// -------------------- scratch ----------------------------------------------
__device__ __half g_ebh[(size_t)NC * DIM];          // fp16 codebook [code][dim]
__device__ float  g_embedT[(size_t)NC * DIM];       // fp32 codebook [code][dim]
__device__ float  g_cnh[NC];                        // 0.5*||e||^2
__device__ int    g_idx[N_TOK];
__device__ float  g_partials[N_TOK];
__device__ int    g_count;
__device__ int    g_list[N_TOK];
__device__ unsigned long long g_best[N_TOK];

// -------------------- helpers ----------------------------------------------
__device__ __forceinline__ uint32_t smem_u32(const void* p) {
    uint32_t a;
    asm("{ .reg .u64 t; cvta.to.shared.u64 t, %1; cvt.u32.u64 %0, t; }"
        : "=r"(a) : "l"(p));
    return a;
}
__device__ __forceinline__ uint32_t swz(uint32_t b) { return b ^ ((b >> 3) & 0x70); }

__device__ __forceinline__ void ldsm4(uint32_t* r, uint32_t a) {
    asm volatile("ldmatrix.sync.aligned.m8n8.x4.shared.b16 {%0,%1,%2,%3}, [%4];"
        : "=r"(r[0]), "=r"(r[1]), "=r"(r[2]), "=r"(r[3]) : "r"(a));
}
__device__ __forceinline__ void mma16816(float* c, const uint32_t* a, const uint32_t* b) {
    asm volatile("mma.sync.aligned.m16n8k16.row.col.f32.f16.f16.f32 "
        "{%0,%1,%2,%3}, {%4,%5,%6,%7}, {%8,%9}, {%0,%1,%2,%3};"
        : "+f"(c[0]), "+f"(c[1]), "+f"(c[2]), "+f"(c[3])
        : "r"(a[0]), "r"(a[1]), "r"(a[2]), "r"(a[3]), "r"(b[0]), "r"(b[1]));
}
__device__ __forceinline__ void cpa16(uint32_t s, const void* g) {
    asm volatile("cp.async.cg.shared.global [%0], [%1], 16;" :: "r"(s), "l"(g));
}
#define CP_COMMIT() asm volatile("cp.async.commit_group;" ::: "memory")
#define CP_WAIT2()  asm volatile("cp.async.wait_group 2;" ::: "memory")
#define CP_WAIT1()  asm volatile("cp.async.wait_group 1;" ::: "memory")
#define CP_WAIT0()  asm volatile("cp.async.wait_group 0;" ::: "memory")

// monotonic (score, smaller-idx-wins) packing for atomicMax merge
__device__ __forceinline__ unsigned long long pack_si(float s, int idx) {
    uint32_t u = __float_as_uint(s);
    u = (s < 0.0f) ? ~u : (u | 0x80000000u);
    return ((unsigned long long)u << 32) | (uint32_t)(NC - 1 - idx);
}

// ---------------------------------------------------------------------------
// K0a: transpose codebook + fp16 cast; zero compaction counter
// ---------------------------------------------------------------------------
__global__ void prep_transpose(const float* __restrict__ embed) {
    __shared__ float ts[64][65];
    if (blockIdx.x == 0 && blockIdx.y == 0 && threadIdx.x == 0) g_count = 0;
    int c0 = blockIdx.x * 64, d0 = blockIdx.y * 64;
    int a = threadIdx.x & 63, b = threadIdx.x >> 6;
    #pragma unroll
    for (int i = 0; i < 16; ++i) {
        int d = b + i * 4;
        ts[d][a] = embed[(size_t)(d0 + d) * NC + c0 + a];
    }
    __syncthreads();
    #pragma unroll
    for (int i = 0; i < 16; ++i) {
        int cI = b + i * 4;
        float v = ts[a][cI];
        size_t o = (size_t)(c0 + cI) * DIM + d0 + a;
        g_embedT[o] = v;
        g_ebh[o] = __float2half_rn(v);
    }
}

// ---------------------------------------------------------------------------
// K0b: 0.5*||e||^2
// ---------------------------------------------------------------------------
__global__ void prep_cnorm(void) {
    int w = threadIdx.x >> 5, l = threadIdx.x & 31;
    int c = blockIdx.x * 8 + w;
    const float4* er = reinterpret_cast<const float4*>(g_embedT + (size_t)c * DIM);
    float4 p = er[l], q = er[l + 32];
    float s = p.x*p.x + p.y*p.y + p.z*p.z + p.w*p.w
            + q.x*q.x + q.y*q.y + q.z*q.z + q.w*q.w;
    #pragma unroll
    for (int off = 16; off; off >>= 1) s += __shfl_down_sync(0xffffffffu, s, off);
    if (l == 0) g_cnh[c] = 0.5f * s;
}

// ---------------------------------------------------------------------------
// K1: fp16 single-pass HMMA GEMM + running top-2 argmax + flag compaction
// ---------------------------------------------------------------------------
__global__ __launch_bounds__(256, 1)
void vq_hmma(const float* __restrict__ x) {
    extern __shared__ char smem[];
    const uint32_t sbase = smem_u32(smem);
    const int tid = threadIdx.x, lane = tid & 31, wid = tid >> 5;
    const int warp_m = wid & 3, warp_n = wid >> 2;
    const int tokBase = blockIdx.x * M_CTA;

    // cnorm -> smem
    {
        float4* cs = reinterpret_cast<float4*>(smem + SM_CN);
        const float4* cg = reinterpret_cast<const float4*>(g_cnh);
        #pragma unroll
        for (int i = 0; i < 4; ++i) cs[tid + i * 256] = cg[tid + i * 256];
    }

    // A (x tile) -> fp16, SW128 K-major, 4 k-blocks of 64 dims
    {
        int r = tid >> 1, half = tid & 1;
        const float4* xr = reinterpret_cast<const float4*>(x + (size_t)(tokBase + r) * DIM);
        #pragma unroll
        for (int q = 0; q < 32; ++q) {
            float4 v = xr[half * 32 + q];
            int d = half * 128 + q * 4;
            int kb = d >> 6, kd = d & 63;
            uint32_t off = kb * 16384 + swz((uint32_t)(r * 128 + kd * 2));
            __half h0 = __float2half_rn(v.x), h1 = __float2half_rn(v.y);
            __half h2 = __float2half_rn(v.z), h3 = __float2half_rn(v.w);
            uint32_t p0 = ((uint32_t)__half_as_ushort(h1) << 16) | __half_as_ushort(h0);
            uint32_t p1 = ((uint32_t)__half_as_ushort(h3) << 16) | __half_as_ushort(h2);
            *reinterpret_cast<uint32_t*>(smem + SM_A + off)     = p0;
            *reinterpret_cast<uint32_t*>(smem + SM_A + off + 4) = p1;
        }
    }
    __syncthreads();

    const float* cnh = reinterpret_cast<const float*>(smem + SM_CN);

    float acc[2][8][4];
    float best[4], sec[4];
    int   bi[4];
    #pragma unroll
    for (int i = 0; i < 4; ++i) { best[i] = -1e30f; sec[i] = -1e30f; bi[i] = 0; }

    const int seg = tid & 7, rb = tid >> 3;

    auto loadB = [&](int j) {
        int c0 = (j >> 2) * NCHUNK, kb = j & 3;
        uint32_t bb = sbase + SM_B + (j & 3) * 16384;
        #pragma unroll
        for (int i = 0; i < 4; ++i) {
            int row = rb + 32 * i;
            size_t go = ((size_t)(c0 + row) << 8) + kb * 64 + seg * 8;
            uint32_t so = swz((uint32_t)(row * 128 + seg * 16));
            cpa16(bb + so, g_ebh + go);
        }
    };

    loadB(0); CP_COMMIT();
    loadB(1); CP_COMMIT();
    loadB(2); CP_COMMIT();

    const int r16 = lane & 15, cg8 = (lane >> 4) << 3;

    for (int j = 0; j < TOTJ; ++j) {
        int rem = TOTJ - 1 - j;
        if (rem >= 2)      CP_WAIT2();
        else if (rem == 1) CP_WAIT1();
        else               CP_WAIT0();
        __syncthreads();
        if (j + 3 < TOTJ) { loadB(j + 3); CP_COMMIT(); }

        const int kb = j & 3;
        const uint32_t aB = sbase + SM_A + kb * 16384;
        const uint32_t bB = sbase + SM_B + (j & 3) * 16384;

        if (kb == 0) {
            #pragma unroll
            for (int mt = 0; mt < 2; ++mt)
                #pragma unroll
                for (int nt = 0; nt < 8; ++nt)
                    #pragma unroll
                    for (int e = 0; e < 4; ++e) acc[mt][nt][e] = 0.0f;
        }

        #pragma unroll
        for (int ks = 0; ks < 4; ++ks) {
            const int kcol = ks * 16 + cg8;
            uint32_t ah[2][4], bh[8][2];
            #pragma unroll
            for (int mt = 0; mt < 2; ++mt) {
                uint32_t off = swz((uint32_t)((warp_m * 32 + mt * 16 + r16) * 128 + kcol * 2));
                ldsm4(ah[mt], aB + off);
            }
            #pragma unroll
            for (int p = 0; p < 4; ++p) {
                uint32_t off = swz((uint32_t)((warp_n * 64 + p * 16 + r16) * 128 + kcol * 2));
                uint32_t t[4];
                ldsm4(t, bB + off);
                bh[2*p][0]   = t[0]; bh[2*p][1]   = t[2];
                bh[2*p+1][0] = t[1]; bh[2*p+1][1] = t[3];
            }
            #pragma unroll
            for (int mt = 0; mt < 2; ++mt)
                #pragma unroll
                for (int nt = 0; nt < 8; ++nt)
                    mma16816(acc[mt][nt], ah[mt], bh[nt]);
        }

        if (kb == 3) {
            const int c0 = (j >> 2) * NCHUNK + warp_n * 64 + (lane & 3) * 2;
            #pragma unroll
            for (int nt = 0; nt < 8; ++nt) {
                const int col0 = c0 + nt * 8;
                const float cn0 = cnh[col0], cn1 = cnh[col0 + 1];
                #pragma unroll
                for (int mt = 0; mt < 2; ++mt) {
                    const int s0 = mt * 2, s1 = mt * 2 + 1;
                    float v;
                    v = acc[mt][nt][0] - cn0;
                    if (v > best[s0]) { sec[s0] = best[s0]; best[s0] = v; bi[s0] = col0; }
                    else if (v > sec[s0]) sec[s0] = v;
                    v = acc[mt][nt][1] - cn1;
                    if (v > best[s0]) { sec[s0] = best[s0]; best[s0] = v; bi[s0] = col0 + 1; }
                    else if (v > sec[s0]) sec[s0] = v;
                    v = acc[mt][nt][2] - cn0;
                    if (v > best[s1]) { sec[s1] = best[s1]; best[s1] = v; bi[s1] = col0; }
                    else if (v > sec[s1]) sec[s1] = v;
                    v = acc[mt][nt][3] - cn1;
                    if (v > best[s1]) { sec[s1] = best[s1]; best[s1] = v; bi[s1] = col0 + 1; }
                    else if (v > sec[s1]) sec[s1] = v;
                }
            }
        }
    }
    __syncthreads();

    // intra-quad top-2 merge
    #pragma unroll
    for (int s = 0; s < 4; ++s) {
        float b = best[s], se = sec[s];
        int   i = bi[s];
        #pragma unroll
        for (int off = 1; off <= 2; off <<= 1) {
            float ob = __shfl_xor_sync(0xffffffffu, b, off);
            float os = __shfl_xor_sync(0xffffffffu, se, off);
            int   oi = __shfl_xor_sync(0xffffffffu, i, off);
            if (ob > b || (ob == b && oi < i)) { se = fmaxf(b, os); b = ob; i = oi; }
            else                               { se = fmaxf(se, ob); }
        }
        best[s] = b; sec[s] = se; bi[s] = i;
    }

    float* mb = reinterpret_cast<float*>(smem + SM_B);
    float* ms = mb + 128;
    int*   mi = reinterpret_cast<int*>(ms + 128);
    if (warp_n == 0 && (lane & 3) == 0) {
        #pragma unroll
        for (int s = 0; s < 4; ++s) {
            int row = warp_m * 32 + (s >> 1) * 16 + (s & 1) * 8 + (lane >> 2);
            mb[row] = best[s]; ms[row] = sec[s]; mi[row] = bi[s];
        }
    }
    __syncthreads();
    if (warp_n == 1 && (lane & 3) == 0) {
        #pragma unroll
        for (int s = 0; s < 4; ++s) {
            int row = warp_m * 32 + (s >> 1) * 16 + (s & 1) * 8 + (lane >> 2);
            float b = best[s], se = sec[s];
            int   i = bi[s];
            float ob = mb[row], os = ms[row];
            int   oi = mi[row];
            if (ob > b || (ob == b && oi < i)) { se = fmaxf(b, os); b = ob; i = oi; }
            else                               { se = fmaxf(se, ob); }
            int t = tokBase + row;
            g_idx[t] = i;
            if (b - se < MARGIN) {
                g_best[t] = 0ULL;                     // init merge slot (pre-fixup)
                int p = atomicAdd(&g_count, 1);
                g_list[p] = t;
            }
        }
    }
}

// ---------------------------------------------------------------------------
// K2: exact fp32 rescore; CTA = 8 tokens x 1024 codes (4 CTAs per group),
//     partial winners merged via order-independent atomicMax(u64).
// ---------------------------------------------------------------------------
__global__ __launch_bounds__(256)
void fixup_micro(const float* __restrict__ x) {
    int cnt = g_count;
    int grp = blockIdx.x >> 2;
    int part = blockIdx.x & 3;
    if (grp >= ((cnt + 7) >> 3)) return;

    __shared__ float Xs[256][8];     // [dim][tok]
    __shared__ float Es[8][1024];    // 8-dim k-slice of this CTA's 1024 codes
    __shared__ int   toks[8];
    __shared__ float wb[8][8];
    __shared__ int   wi[8][8];

    const int tid = threadIdx.x, lane = tid & 31, wid = tid >> 5;
    const int cbase = part * 1024;

    if (tid < 8) {
        int li = grp * 8 + tid;
        toks[tid] = g_list[li < cnt ? li : 0];
    }
    __syncthreads();
    {
        int tk = tid & 7, d0 = (tid >> 3) * 8;
        const float* xr = x + (size_t)toks[tk] * DIM + d0;
        #pragma unroll
        for (int i = 0; i < 8; ++i) Xs[d0 + i][tk] = xr[i];
    }

    float acc[8][4];
    #pragma unroll
    for (int t = 0; t < 8; ++t)
        #pragma unroll
        for (int jj = 0; jj < 4; ++jj) acc[t][jj] = 0.0f;

    for (int k0 = 0; k0 < DIM; k0 += 8) {
        __syncthreads();
        #pragma unroll
        for (int jj = 0; jj < 4; ++jj) {
            int c = tid + 256 * jj;
            const float4* er = reinterpret_cast<const float4*>(
                g_embedT + (size_t)(cbase + c) * DIM + k0);
            float4 a = er[0], b = er[1];
            Es[0][c] = a.x; Es[1][c] = a.y; Es[2][c] = a.z; Es[3][c] = a.w;
            Es[4][c] = b.x; Es[5][c] = b.y; Es[6][c] = b.z; Es[7][c] = b.w;
        }
        __syncthreads();
        #pragma unroll
        for (int kk = 0; kk < 8; ++kk) {
            float4 e4 = *reinterpret_cast<const float4*>(&Es[kk][tid * 4]);
            float xv[8];
            #pragma unroll
            for (int t = 0; t < 8; ++t) xv[t] = Xs[k0 + kk][t];
            #pragma unroll
            for (int t = 0; t < 8; ++t) {
                acc[t][0] = fmaf(xv[t], e4.x, acc[t][0]);
                acc[t][1] = fmaf(xv[t], e4.y, acc[t][1]);
                acc[t][2] = fmaf(xv[t], e4.z, acc[t][2]);
                acc[t][3] = fmaf(xv[t], e4.w, acc[t][3]);
            }
        }
    }

    float best[8]; int bi[8];
    #pragma unroll
    for (int t = 0; t < 8; ++t) { best[t] = -1e30f; bi[t] = 0; }
    #pragma unroll
    for (int jj = 0; jj < 4; ++jj) {
        int c = cbase + tid * 4 + jj;
        float cn = g_cnh[c];
        #pragma unroll
        for (int t = 0; t < 8; ++t) {
            float s = acc[t][jj] - cn;
            if (s > best[t]) { best[t] = s; bi[t] = c; }
        }
    }

    #pragma unroll
    for (int t = 0; t < 8; ++t) {
        float b = best[t]; int i = bi[t];
        #pragma unroll
        for (int off = 16; off; off >>= 1) {
            float ob = __shfl_down_sync(0xffffffffu, b, off);
            int   oi = __shfl_down_sync(0xffffffffu, i, off);
            if (ob > b || (ob == b && oi < i)) { b = ob; i = oi; }
        }
        if (lane == 0) { wb[wid][t] = b; wi[wid][t] = i; }
    }
    __syncthreads();
    if (wid == 0 && lane < 8) {
        int t = lane;
        float b = wb[0][t]; int i = wi[0][t];
        #pragma unroll
        for (int w = 1; w < 8; ++w) {
            float ob = wb[w][t]; int oi = wi[w][t];
            if (ob > b || (ob == b && oi < i)) { b = ob; i = oi; }
        }
        atomicMax(&g_best[toks[t]], pack_si(b, i));
    }
}

// ---------------------------------------------------------------------------
// K2b: unpack merged winners into g_idx
// ---------------------------------------------------------------------------
__global__ void fixup_apply(void) {
    int cnt = g_count;
    for (int i = blockIdx.x * 256 + threadIdx.x; i < cnt; i += gridDim.x * 256) {
        int t = g_list[i];
        g_idx[t] = NC - 1 - (int)(uint32_t)(g_best[t] & 0xFFFFFFFFULL);
    }
}

// ---------------------------------------------------------------------------
// K3: gather quantize + diff partials + indices
// ---------------------------------------------------------------------------
__global__ __launch_bounds__(256)
void quantize_kernel(const float* __restrict__ x, float* __restrict__ out) {
    int gt = blockIdx.x * 8 + (threadIdx.x >> 5);
    int l = threadIdx.x & 31;
    int idx = g_idx[gt];
    const float4* er = reinterpret_cast<const float4*>(g_embedT + (size_t)idx * DIM);
    const float4* xr = reinterpret_cast<const float4*>(x + (size_t)gt * DIM);
    float4* qw = reinterpret_cast<float4*>(out + (size_t)gt * DIM);
    float s = 0.0f;
    #pragma unroll
    for (int i = 0; i < 2; ++i) {
        int k = l + 32 * i;
        float4 q = er[k], xv = xr[k];
        float d0 = q.x - xv.x, d1 = q.y - xv.y, d2 = q.z - xv.z, d3 = q.w - xv.w;
        s = fmaf(d0, d0, s); s = fmaf(d1, d1, s);
        s = fmaf(d2, d2, s); s = fmaf(d3, d3, s);
        qw[k] = q;
    }
    #pragma unroll
    for (int off = 16; off; off >>= 1) s += __shfl_down_sync(0xffffffffu, s, off);
    if (l == 0) {
        g_partials[gt] = s;
        out[QELEMS + 1 + (size_t)gt] = (float)idx;
    }
}

// ---------------------------------------------------------------------------
// K4: deterministic diff reduction
// ---------------------------------------------------------------------------
__global__ void finalize_kernel(float* __restrict__ out) {
    __shared__ float sh[256];
    int tid = threadIdx.x;
    const float4* p4 = reinterpret_cast<const float4*>(g_partials);
    float s = 0.0f;
    for (int j = 0; j < 64; ++j) {
        float4 v = p4[tid + 256 * j];
        s += v.x + v.y + v.z + v.w;
    }
    sh[tid] = s;
    __syncthreads();
    for (int off = 128; off; off >>= 1) {
        if (tid < off) sh[tid] += sh[tid + off];
        __syncthreads();
    }
    if (tid == 0) out[QELEMS] = sh[0] / (float)QELEMS;
}

// ---------------------------------------------------------------------------
extern "C" void kernel_launch(void* const* d_in, const int* in_sizes, int n_in,
                              void* d_out, int out_size) {
    const float* x     = (const float*)d_in[0];
    const float* embed = (const float*)d_in[1];
    float* out = (float*)d_out;

    cudaFuncSetAttribute(vq_hmma, cudaFuncAttributeMaxDynamicSharedMemorySize,
                         SMEM_TOTAL);

    prep_transpose<<<dim3(NC / 64, DIM / 64), 256>>>(embed);
    prep_cnorm<<<NC / 8, 256>>>();
    vq_hmma<<<K1_GRID, 256, SMEM_TOTAL>>>(x);
    fixup_micro<<<(N_TOK / 8) * 4, 256>>>(x);
    fixup_apply<<<64, 256>>>();
    quantize_kernel<<<N_TOK / 8, 256>>>(x, out);
    finalize_kernel<<<1, 256>>>(out);
}